// round 5
// baseline (speedup 1.0000x reference)
#include <cuda_runtime.h>
#include <cuda_bf16.h>
#include <math.h>
#include <stdint.h>

#define B_  64
#define S_  256
#define H_  768
#define T_  13
#define D_  64
#define NEGC 1000000000000.0f

#define M1 (B_*S_)      // 16384
#define N1 (T_*2*D_)    // 1664
#define K1 H_           // 768

typedef __nv_bfloat16  bf16;
typedef __nv_bfloat162 bf162;

// ------------------------- device scratch (no allocs) ----------------------
__device__ __align__(128) bf16 g_xb[(size_t)M1 * K1];   // X bf16 [16384,768]
__device__ __align__(128) bf16 g_wt[(size_t)N1 * K1];   // W^T bf16 [1664,768]
__device__ float g_cos[S_ * (D_/2)];
__device__ float g_sin[S_ * (D_/2)];

// ------------------------------ PTX helpers --------------------------------
__device__ __forceinline__ uint32_t smem_u32(const void* p) {
    return (uint32_t)__cvta_generic_to_shared(p);
}
__device__ __forceinline__ void cp16(uint32_t dst, const void* src) {
    asm volatile("cp.async.cg.shared.global [%0], [%1], 16;\n" :: "r"(dst), "l"(src));
}
__device__ __forceinline__ void cp_commit() {
    asm volatile("cp.async.commit_group;\n");
}
template<int N> __device__ __forceinline__ void cp_wait() {
    asm volatile("cp.async.wait_group %0;\n" :: "n"(N));
}
__device__ __forceinline__ void ldm_x4(uint32_t addr,
        uint32_t& r0, uint32_t& r1, uint32_t& r2, uint32_t& r3) {
    asm volatile("ldmatrix.sync.aligned.m8n8.x4.shared.b16 {%0,%1,%2,%3}, [%4];\n"
        : "=r"(r0), "=r"(r1), "=r"(r2), "=r"(r3) : "r"(addr));
}
__device__ __forceinline__ void mma_bf16(float* c,
        uint32_t a0, uint32_t a1, uint32_t a2, uint32_t a3,
        uint32_t b0, uint32_t b1) {
    asm volatile(
        "mma.sync.aligned.m16n8k16.row.col.f32.bf16.bf16.f32 "
        "{%0,%1,%2,%3}, {%4,%5,%6,%7}, {%8,%9}, {%0,%1,%2,%3};\n"
        : "+f"(c[0]), "+f"(c[1]), "+f"(c[2]), "+f"(c[3])
        : "r"(a0), "r"(a1), "r"(a2), "r"(a3), "r"(b0), "r"(b1));
}

// ---------------------------------------------------------------------------
// Prep kernel: X fp32->bf16, W transpose+convert, RoPE table — one launch.
// blocks [0,12288): X | [12288,13536): W tiles | [13536,13568): rope
// ---------------------------------------------------------------------------
__global__ __launch_bounds__(256) void prep_kernel(
    const float* __restrict__ X, const float* __restrict__ W)
{
    const int bx  = blockIdx.x;
    const int tid = threadIdx.x;

    if (bx < 12288) {                       // ---- X convert, float4 each
        int i = bx * 256 + tid;
        float4 v = reinterpret_cast<const float4*>(X)[i];
        bf162* o = reinterpret_cast<bf162*>(g_xb) + (size_t)i * 2;
        o[0] = __floats2bfloat162_rn(v.x, v.y);
        o[1] = __floats2bfloat162_rn(v.z, v.w);
    } else if (bx < 13536) {                // ---- W [768,1664] -> W^T bf16
        __shared__ float t[32][33];
        int bw = bx - 12288;
        int x0 = (bw % 52) * 32;            // N dim
        int y0 = (bw / 52) * 32;            // K dim
        int tx = tid & 31, ty = tid >> 5;   // 32 x 8
        #pragma unroll
        for (int i = 0; i < 4; i++)
            t[ty + i*8][tx] = W[(size_t)(y0 + ty + i*8) * N1 + x0 + tx];
        __syncthreads();
        #pragma unroll
        for (int i = 0; i < 4; i++)
            g_wt[(size_t)(x0 + ty + i*8) * K1 + y0 + tx] =
                __float2bfloat16(t[tx][ty + i*8]);
    } else {                                 // ---- RoPE table (fp64)
        int idx = (bx - 13536) * 256 + tid;
        if (idx < S_ * (D_/2)) {
            int s = idx >> 5;
            int i = idx & 31;
            double inv = pow(10000.0, -2.0 * (double)i / (double)D_);
            double ang = (double)s * inv;
            g_cos[idx] = (float)cos(ang);
            g_sin[idx] = (float)sin(ang);
        }
    }
}

// ---------------------------------------------------------------------------
// Fused kernel: one CTA per (batch, head).
//   Stage 1: C[256,128] = X_b @ Wh + bias (K=768), bf16 mma.sync,
//            warp tile 64x64 (8 warps, 4x2), cp.async double buffer BK=64.
//   Stage 2: RoPE -> q,k bf16 into smem (reusing A buffers).
//   Stage 3: logits[256,256] = q @ k^T (K=64), masks + 0.125, write out.
// ---------------------------------------------------------------------------
__global__ __launch_bounds__(256) void fused_gp_kernel(
    const float* __restrict__ bias, const float* __restrict__ attn_mask,
    float* __restrict__ out)
{
    extern __shared__ __align__(16) char dyn[];
    __shared__ float s_bias[128];
    __shared__ float pads[256];

    char* base = (char*)(((uintptr_t)dyn + 1023) & ~(uintptr_t)1023);
    bf16* smA = (bf16*)base;                 // 2 bufs x 256x64 = 64KB
    bf16* smB = (bf16*)(base + 65536);       // 2 bufs x 128x64 = 32KB

    const int tid  = threadIdx.x;
    const int lane = tid & 31;
    const int warp = tid >> 5;
    const int wm   = warp & 3;     // M: 4 x 64 rows
    const int wn   = warp >> 2;    // N: 2 x 64 cols
    const int h    = blockIdx.x;   // head
    const int bb   = blockIdx.y;   // batch

    const bf16* gA = g_xb + (size_t)bb * 256 * K1;
    const bf16* gB = g_wt + (size_t)h * 128 * K1;

    auto load_tile = [&](int buf, int k0) {
        bf16* dA = smA + buf * (256 * 64);
        bf16* dB = smB + buf * (128 * 64);
        #pragma unroll
        for (int t = 0; t < 8; t++) {              // A: 2048 16B chunks
            int f = tid + t * 256;
            int r = f >> 3, c = f & 7;
            int sw = (c ^ (r & 7)) << 3;
            cp16(smem_u32(dA + r * 64 + sw), gA + (size_t)r * K1 + k0 + c * 8);
        }
        #pragma unroll
        for (int t = 0; t < 4; t++) {              // B: 1024 chunks
            int f = tid + t * 256;
            int r = f >> 3, c = f & 7;
            int sw = (c ^ (r & 7)) << 3;
            cp16(smem_u32(dB + r * 64 + sw), gB + (size_t)r * K1 + k0 + c * 8);
        }
    };

    load_tile(0, 0);
    cp_commit();

    if (tid < 128) s_bias[tid] = bias[h * 128 + tid];
    pads[tid] = attn_mask[bb * 256 + tid];

    float acc[4][8][4];
    #pragma unroll
    for (int i = 0; i < 4; i++)
        #pragma unroll
        for (int j = 0; j < 8; j++)
            #pragma unroll
            for (int c = 0; c < 4; c++) acc[i][j][c] = 0.0f;

    // ---------------- Stage 1 mainloop: 12 x BK=64 --------------------------
    for (int it = 0; it < 12; it++) {
        if (it < 11) {
            load_tile((it + 1) & 1, (it + 1) * 64);
            cp_commit();
            cp_wait<1>();
        } else {
            cp_wait<0>();
        }
        __syncthreads();

        const bf16* A  = smA + (it & 1) * (256 * 64);
        const bf16* Bs = smB + (it & 1) * (128 * 64);
        #pragma unroll
        for (int ki = 0; ki < 4; ki++) {
            uint32_t a[4][4];
            #pragma unroll
            for (int mi = 0; mi < 4; mi++) {
                int row = wm * 64 + mi * 16 + (lane & 15);
                int kch = ki * 2 + (lane >> 4);
                uint32_t ad = smem_u32(A + row * 64 + ((kch ^ (row & 7)) << 3));
                ldm_x4(ad, a[mi][0], a[mi][1], a[mi][2], a[mi][3]);
            }
            #pragma unroll
            for (int njp = 0; njp < 4; njp++) {
                int mat  = lane >> 3;
                int rowb = wn * 64 + njp * 16 + ((mat >> 1) << 3) + (lane & 7);
                int kch  = ki * 2 + (mat & 1);
                uint32_t bd = smem_u32(Bs + rowb * 64 + ((kch ^ (rowb & 7)) << 3));
                uint32_t b0, b1, b2, b3;
                ldm_x4(bd, b0, b1, b2, b3);
                #pragma unroll
                for (int mi = 0; mi < 4; mi++) {
                    mma_bf16(acc[mi][njp*2],   a[mi][0], a[mi][1], a[mi][2], a[mi][3], b0, b1);
                    mma_bf16(acc[mi][njp*2+1], a[mi][0], a[mi][1], a[mi][2], a[mi][3], b2, b3);
                }
            }
        }
        __syncthreads();
    }

    // ---------------- Stage 2: bias + RoPE -> q/k smem ----------------------
    bf16* Qs = smA;              // 256 x 64
    bf16* Ks = smA + 16384;      // 256 x 64
    #pragma unroll
    for (int mi = 0; mi < 4; mi++) {
        #pragma unroll
        for (int nj = 0; nj < 8; nj++) {
            int col = wn * 64 + nj * 8 + ((lane & 3) << 1);   // 0..127, even
            int d   = col & 63;
            bf16* dst = (col < 64) ? Qs : Ks;
            float bx = s_bias[col];
            float by = s_bias[col + 1];
            int pi    = d >> 1;
            int chunk = d >> 3;
            int dlo   = d & 7;
            #pragma unroll
            for (int hh = 0; hh < 2; hh++) {
                int srow = wm * 64 + mi * 16 + (lane >> 2) + hh * 8;
                float x = acc[mi][nj][hh*2]     + bx;
                float y = acc[mi][nj][hh*2 + 1] + by;
                float cs = g_cos[srow * 32 + pi];
                float sn = g_sin[srow * 32 + pi];
                bf162 v;
                v.x = __float2bfloat16(x * cs - y * sn);
                v.y = __float2bfloat16(y * cs + x * sn);
                *reinterpret_cast<bf162*>(
                    &dst[srow * 64 + ((chunk ^ (srow & 7)) << 3) + dlo]) = v;
            }
        }
    }
    __syncthreads();

    // ---------------- Stage 3: logits = q @ k^T, 2 passes of N=128 ----------
    const size_t zbase = ((size_t)(bb * T_ + h)) << 16;   // *65536
    #pragma unroll
    for (int pass = 0; pass < 2; pass++) {
        #pragma unroll
        for (int i = 0; i < 4; i++)
            #pragma unroll
            for (int j = 0; j < 8; j++)
                #pragma unroll
                for (int c = 0; c < 4; c++) acc[i][j][c] = 0.0f;

        #pragma unroll
        for (int ki = 0; ki < 4; ki++) {
            uint32_t a[4][4];
            #pragma unroll
            for (int mi = 0; mi < 4; mi++) {
                int row = wm * 64 + mi * 16 + (lane & 15);
                int kch = ki * 2 + (lane >> 4);
                uint32_t ad = smem_u32(Qs + row * 64 + ((kch ^ (row & 7)) << 3));
                ldm_x4(ad, a[mi][0], a[mi][1], a[mi][2], a[mi][3]);
            }
            #pragma unroll
            for (int njp = 0; njp < 4; njp++) {
                int mat  = lane >> 3;
                int rowb = pass * 128 + wn * 64 + njp * 16 + ((mat >> 1) << 3) + (lane & 7);
                int kch  = ki * 2 + (mat & 1);
                uint32_t bd = smem_u32(Ks + rowb * 64 + ((kch ^ (rowb & 7)) << 3));
                uint32_t b0, b1, b2, b3;
                ldm_x4(bd, b0, b1, b2, b3);
                #pragma unroll
                for (int mi = 0; mi < 4; mi++) {
                    mma_bf16(acc[mi][njp*2],   a[mi][0], a[mi][1], a[mi][2], a[mi][3], b0, b1);
                    mma_bf16(acc[mi][njp*2+1], a[mi][0], a[mi][1], a[mi][2], a[mi][3], b2, b3);
                }
            }
        }

        // epilogue: pad + strict-lower causal + scale, float2 stores
        #pragma unroll
        for (int mi = 0; mi < 4; mi++) {
            #pragma unroll
            for (int nj = 0; nj < 8; nj++) {
                int n  = pass * 128 + wn * 64 + nj * 8 + ((lane & 3) << 1);
                float p0 = pads[n];
                float p1 = pads[n + 1];
                #pragma unroll
                for (int hh = 0; hh < 2; hh++) {
                    int m = wm * 64 + mi * 16 + (lane >> 2) + hh * 8;
                    float x = acc[mi][nj][hh*2];
                    float y = acc[mi][nj][hh*2 + 1];
                    float t0 = x * p0 - (1.0f - p0) * NEGC;
                    float t1 = y * p1 - (1.0f - p1) * NEGC;
                    if (m > n)     t0 -= NEGC;
                    if (m > n + 1) t1 -= NEGC;
                    float2 v = make_float2(t0 * 0.125f, t1 * 0.125f);
                    *reinterpret_cast<float2*>(&out[zbase + (size_t)m * 256 + n]) = v;
                }
            }
        }
    }
}

// ---------------------------------------------------------------------------
extern "C" void kernel_launch(void* const* d_in, const int* in_sizes, int n_in,
                              void* d_out, int out_size) {
    const float* X    = (const float*)d_in[0];   // [B,S,H]
    const float* W    = (const float*)d_in[1];   // [H, T*2*D]
    const float* bias = (const float*)d_in[2];   // [T*2*D]
    const float* mask = (const float*)d_in[3];   // [B,S]
    float* out = (float*)d_out;                  // [B,T,S,S]

    prep_kernel<<<13568, 256>>>(X, W);

    cudaFuncSetAttribute(fused_gp_kernel,
                         cudaFuncAttributeMaxDynamicSharedMemorySize, 99328);
    fused_gp_kernel<<<dim3(13, 64), 256, 99328>>>(bias, mask, out);
}

// round 6
// speedup vs baseline: 1.1144x; 1.1144x over previous
#include <cuda_runtime.h>
#include <cuda_fp16.h>
#include <math.h>
#include <stdint.h>

#define B_  64
#define S_  256
#define H_  768
#define T_  13
#define D_  64
#define NEGC 1000000000000.0f

#define M1 (B_*S_)      // 16384
#define N1 (T_*2*D_)    // 1664
#define K1 H_           // 768

// ------------------------- device scratch (no allocs) ----------------------
__device__ __align__(128) half g_xh[(size_t)M1 * K1];   // X f16 [16384,768]
__device__ __align__(128) half g_wh[(size_t)N1 * K1];   // W^T f16 [1664,768]
__device__ float g_cos[S_ * (D_/2)];
__device__ float g_sin[S_ * (D_/2)];

// ------------------------------ PTX helpers --------------------------------
__device__ __forceinline__ uint32_t smem_u32(const void* p) {
    return (uint32_t)__cvta_generic_to_shared(p);
}
__device__ __forceinline__ void cp16(uint32_t dst, const void* src) {
    asm volatile("cp.async.cg.shared.global [%0], [%1], 16;\n" :: "r"(dst), "l"(src));
}
__device__ __forceinline__ void cp_commit() {
    asm volatile("cp.async.commit_group;\n");
}
template<int N> __device__ __forceinline__ void cp_wait() {
    asm volatile("cp.async.wait_group %0;\n" :: "n"(N));
}
__device__ __forceinline__ void ldm_x4(uint32_t addr,
        uint32_t& r0, uint32_t& r1, uint32_t& r2, uint32_t& r3) {
    asm volatile("ldmatrix.sync.aligned.m8n8.x4.shared.b16 {%0,%1,%2,%3}, [%4];\n"
        : "=r"(r0), "=r"(r1), "=r"(r2), "=r"(r3) : "r"(addr));
}
// f16 x f16 -> f16 accumulate: D/C = 2 regs (f16x2 pairs)
__device__ __forceinline__ void mma_h(uint32_t& c0, uint32_t& c1,
        uint32_t a0, uint32_t a1, uint32_t a2, uint32_t a3,
        uint32_t b0, uint32_t b1) {
    asm volatile(
        "mma.sync.aligned.m16n8k16.row.col.f16.f16.f16.f16 "
        "{%0,%1}, {%2,%3,%4,%5}, {%6,%7}, {%0,%1};\n"
        : "+r"(c0), "+r"(c1)
        : "r"(a0), "r"(a1), "r"(a2), "r"(a3), "r"(b0), "r"(b1));
}

// ---------------------------------------------------------------------------
// Prep: X fp32->f16, W transpose+convert->f16, RoPE table — one launch.
// blocks [0,12288): X | [12288,13536): W tiles | [13536,13568): rope
// ---------------------------------------------------------------------------
__global__ __launch_bounds__(256) void prep_kernel(
    const float* __restrict__ X, const float* __restrict__ W)
{
    const int bx  = blockIdx.x;
    const int tid = threadIdx.x;

    if (bx < 12288) {                       // ---- X convert, one float4 each
        int i = bx * 256 + tid;
        float4 v = reinterpret_cast<const float4*>(X)[i];
        half2* o = reinterpret_cast<half2*>(g_xh) + (size_t)i * 2;
        o[0] = __floats2half2_rn(v.x, v.y);
        o[1] = __floats2half2_rn(v.z, v.w);
    } else if (bx < 13536) {                // ---- W [768,1664] -> W^T f16
        __shared__ float t[32][33];
        int bw = bx - 12288;
        int x0 = (bw % 52) * 32;            // N dim
        int y0 = (bw / 52) * 32;            // K dim
        int tx = tid & 31, ty = tid >> 5;   // 32 x 8
        #pragma unroll
        for (int i = 0; i < 4; i++)
            t[ty + i*8][tx] = W[(size_t)(y0 + ty + i*8) * N1 + x0 + tx];
        __syncthreads();
        #pragma unroll
        for (int i = 0; i < 4; i++)
            g_wh[(size_t)(x0 + ty + i*8) * K1 + y0 + tx] =
                __float2half(t[tx][ty + i*8]);
    } else {                                 // ---- RoPE table (fp64)
        int idx = (bx - 13536) * 256 + tid;
        if (idx < S_ * (D_/2)) {
            int s = idx >> 5;
            int i = idx & 31;
            double inv = pow(10000.0, -2.0 * (double)i / (double)D_);
            double ang = (double)s * inv;
            g_cos[idx] = (float)cos(ang);
            g_sin[idx] = (float)sin(ang);
        }
    }
}

// ---------------------------------------------------------------------------
// Fused kernel: one CTA per (batch, head), 256 threads, 2 CTAs/SM.
//   Stage 1: C[256,128] = X_b @ Wh (K=768), f16 mma.sync, f16 acc,
//            warp tile 64x64 (8 warps, 4x2), cp.async double buffer BK=64.
//   Stage 2: bias + RoPE -> q,k f16 into smem (reusing A buffers).
//   Stage 3: logits[256,256] = q @ k^T (K=64), f16 acc, masks + 0.125.
// ---------------------------------------------------------------------------
__global__ __launch_bounds__(256, 2) void fused_gp_kernel(
    const float* __restrict__ bias, const float* __restrict__ attn_mask,
    float* __restrict__ out)
{
    extern __shared__ __align__(16) char dyn[];
    __shared__ float s_bias[128];
    __shared__ float pads[256];

    char* base = (char*)(((uintptr_t)dyn + 1023) & ~(uintptr_t)1023);
    half* smA = (half*)base;                 // 2 bufs x 256x64 = 64KB
    half* smB = (half*)(base + 65536);       // 2 bufs x 128x64 = 32KB

    const int tid  = threadIdx.x;
    const int lane = tid & 31;
    const int warp = tid >> 5;
    const int wm   = warp & 3;     // M: 4 x 64 rows
    const int wn   = warp >> 2;    // N: 2 x 64 cols
    const int h    = blockIdx.x;   // head
    const int bb   = blockIdx.y;   // batch

    const half* gA = g_xh + (size_t)bb * 256 * K1;
    const half* gB = g_wh + (size_t)h * 128 * K1;

    auto load_tile = [&](int buf, int k0) {
        half* dA = smA + buf * (256 * 64);
        half* dB = smB + buf * (128 * 64);
        #pragma unroll
        for (int t = 0; t < 8; t++) {              // A: 2048 16B chunks
            int f = tid + t * 256;
            int r = f >> 3, c = f & 7;
            int sw = (c ^ (r & 7)) << 3;
            cp16(smem_u32(dA + r * 64 + sw), gA + (size_t)r * K1 + k0 + c * 8);
        }
        #pragma unroll
        for (int t = 0; t < 4; t++) {              // B: 1024 chunks
            int f = tid + t * 256;
            int r = f >> 3, c = f & 7;
            int sw = (c ^ (r & 7)) << 3;
            cp16(smem_u32(dB + r * 64 + sw), gB + (size_t)r * K1 + k0 + c * 8);
        }
    };

    load_tile(0, 0);
    cp_commit();

    if (tid < 128) s_bias[tid] = bias[h * 128 + tid];
    pads[tid] = attn_mask[bb * 256 + tid];

    // f16x2 accumulators: [mi][nj][hh], hh=0 -> rows r..r, cols (n,n+1);
    // hh=1 -> rows r+8. 64 registers total.
    uint32_t acc[4][8][2];
    #pragma unroll
    for (int i = 0; i < 4; i++)
        #pragma unroll
        for (int j = 0; j < 8; j++) { acc[i][j][0] = 0u; acc[i][j][1] = 0u; }

    // ---------------- Stage 1 mainloop: 12 x BK=64 --------------------------
    for (int it = 0; it < 12; it++) {
        if (it < 11) {
            load_tile((it + 1) & 1, (it + 1) * 64);
            cp_commit();
            cp_wait<1>();
        } else {
            cp_wait<0>();
        }
        __syncthreads();

        const half* A  = smA + (it & 1) * (256 * 64);
        const half* Bs = smB + (it & 1) * (128 * 64);
        #pragma unroll
        for (int ki = 0; ki < 4; ki++) {
            uint32_t a[4][4];
            #pragma unroll
            for (int mi = 0; mi < 4; mi++) {
                int row = wm * 64 + mi * 16 + (lane & 15);
                int kch = ki * 2 + (lane >> 4);
                uint32_t ad = smem_u32(A + row * 64 + ((kch ^ (row & 7)) << 3));
                ldm_x4(ad, a[mi][0], a[mi][1], a[mi][2], a[mi][3]);
            }
            #pragma unroll
            for (int njp = 0; njp < 4; njp++) {
                int mat  = lane >> 3;
                int rowb = wn * 64 + njp * 16 + ((mat >> 1) << 3) + (lane & 7);
                int kch  = ki * 2 + (mat & 1);
                uint32_t bd = smem_u32(Bs + rowb * 64 + ((kch ^ (rowb & 7)) << 3));
                uint32_t b0, b1, b2, b3;
                ldm_x4(bd, b0, b1, b2, b3);
                #pragma unroll
                for (int mi = 0; mi < 4; mi++) {
                    mma_h(acc[mi][njp*2][0],   acc[mi][njp*2][1],
                          a[mi][0], a[mi][1], a[mi][2], a[mi][3], b0, b1);
                    mma_h(acc[mi][njp*2+1][0], acc[mi][njp*2+1][1],
                          a[mi][0], a[mi][1], a[mi][2], a[mi][3], b2, b3);
                }
            }
        }
        __syncthreads();
    }

    // ---------------- Stage 2: bias + RoPE -> q/k smem ----------------------
    half* Qs = smA;              // 256 x 64
    half* Ks = smA + 16384;      // 256 x 64
    #pragma unroll
    for (int mi = 0; mi < 4; mi++) {
        #pragma unroll
        for (int nj = 0; nj < 8; nj++) {
            int col = wn * 64 + nj * 8 + ((lane & 3) << 1);   // 0..127, even
            int d   = col & 63;
            half* dst = (col < 64) ? Qs : Ks;
            float bx = s_bias[col];
            float by = s_bias[col + 1];
            int pi    = d >> 1;
            int chunk = d >> 3;
            int dlo   = d & 7;
            #pragma unroll
            for (int hh = 0; hh < 2; hh++) {
                int srow = wm * 64 + mi * 16 + (lane >> 2) + hh * 8;
                float2 xy = __half22float2(
                    *reinterpret_cast<half2*>(&acc[mi][nj][hh]));
                float x = xy.x + bx;
                float y = xy.y + by;
                float cs = g_cos[srow * 32 + pi];
                float sn = g_sin[srow * 32 + pi];
                *reinterpret_cast<half2*>(
                    &dst[srow * 64 + ((chunk ^ (srow & 7)) << 3) + dlo]) =
                    __floats2half2_rn(x * cs - y * sn, y * cs + x * sn);
            }
        }
    }
    __syncthreads();

    // ---------------- Stage 3: logits = q @ k^T, 2 passes of N=128 ----------
    const size_t zbase = ((size_t)(bb * T_ + h)) << 16;   // *65536
    #pragma unroll
    for (int pass = 0; pass < 2; pass++) {
        #pragma unroll
        for (int i = 0; i < 4; i++)
            #pragma unroll
            for (int j = 0; j < 8; j++) { acc[i][j][0] = 0u; acc[i][j][1] = 0u; }

        #pragma unroll
        for (int ki = 0; ki < 4; ki++) {
            uint32_t a[4][4];
            #pragma unroll
            for (int mi = 0; mi < 4; mi++) {
                int row = wm * 64 + mi * 16 + (lane & 15);
                int kch = ki * 2 + (lane >> 4);
                uint32_t ad = smem_u32(Qs + row * 64 + ((kch ^ (row & 7)) << 3));
                ldm_x4(ad, a[mi][0], a[mi][1], a[mi][2], a[mi][3]);
            }
            #pragma unroll
            for (int njp = 0; njp < 4; njp++) {
                int mat  = lane >> 3;
                int rowb = pass * 128 + wn * 64 + njp * 16 + ((mat >> 1) << 3) + (lane & 7);
                int kch  = ki * 2 + (mat & 1);
                uint32_t bd = smem_u32(Ks + rowb * 64 + ((kch ^ (rowb & 7)) << 3));
                uint32_t b0, b1, b2, b3;
                ldm_x4(bd, b0, b1, b2, b3);
                #pragma unroll
                for (int mi = 0; mi < 4; mi++) {
                    mma_h(acc[mi][njp*2][0],   acc[mi][njp*2][1],
                          a[mi][0], a[mi][1], a[mi][2], a[mi][3], b0, b1);
                    mma_h(acc[mi][njp*2+1][0], acc[mi][njp*2+1][1],
                          a[mi][0], a[mi][1], a[mi][2], a[mi][3], b2, b3);
                }
            }
        }

        // epilogue: pad + strict-lower causal + scale, float2 stores
        #pragma unroll
        for (int mi = 0; mi < 4; mi++) {
            #pragma unroll
            for (int nj = 0; nj < 8; nj++) {
                int n  = pass * 128 + wn * 64 + nj * 8 + ((lane & 3) << 1);
                float p0 = pads[n];
                float p1 = pads[n + 1];
                #pragma unroll
                for (int hh = 0; hh < 2; hh++) {
                    int m = wm * 64 + mi * 16 + (lane >> 2) + hh * 8;
                    float2 xy = __half22float2(
                        *reinterpret_cast<half2*>(&acc[mi][nj][hh]));
                    float t0 = xy.x * p0 - (1.0f - p0) * NEGC;
                    float t1 = xy.y * p1 - (1.0f - p1) * NEGC;
                    if (m > n)     t0 -= NEGC;
                    if (m > n + 1) t1 -= NEGC;
                    float2 v = make_float2(t0 * 0.125f, t1 * 0.125f);
                    *reinterpret_cast<float2*>(&out[zbase + (size_t)m * 256 + n]) = v;
                }
            }
        }
    }
}

// ---------------------------------------------------------------------------
extern "C" void kernel_launch(void* const* d_in, const int* in_sizes, int n_in,
                              void* d_out, int out_size) {
    const float* X    = (const float*)d_in[0];   // [B,S,H]
    const float* W    = (const float*)d_in[1];   // [H, T*2*D]
    const float* bias = (const float*)d_in[2];   // [T*2*D]
    const float* mask = (const float*)d_in[3];   // [B,S]
    float* out = (float*)d_out;                  // [B,T,S,S]

    prep_kernel<<<13568, 256>>>(X, W);

    cudaFuncSetAttribute(fused_gp_kernel,
                         cudaFuncAttributeMaxDynamicSharedMemorySize, 99328);
    fused_gp_kernel<<<dim3(13, 64), 256, 99328>>>(bias, mask, out);
}